// round 14
// baseline (speedup 1.0000x reference)
#include <cuda_runtime.h>
#include <cuda_fp16.h>
#include <math.h>

#define BB 4
#define CC 8
#define HH 192
#define WW 256
#define HWSZ (HH*WW)
#define GEOMW 0.01f
#define PIXPB 128                 // pixel lanes per block (x2 channel groups = 256 threads)
#define PPT 3                     // pixels per thread
#define NBLKX (HWSZ/(PIXPB*PPT))  // 128 blocks per batch
#define TOTB  (NBLKX*BB)          // 512 blocks total (<= 592 resident at 4/SM)

// Static device scratch (no allocations allowed)
// photometric pack: [b][cg][pix] -> 32 bytes = 4 channels x {I0,gx,gy,pad} fp16
__device__ uint4  g_packh[BB*2*HWSZ*2];
__device__ float4 g_icp  [BB*HWSZ];     // {nx, ny, nz, depth0}, layout [b][pix]
__device__ float  g_pose[BB*16];
__device__ double g_acc [BB*27];
__device__ int    g_cnt [BB];
__device__ int    g_bar_cnt;
__device__ int    g_bar_gen;

// generation-counter grid barrier; safe because all TOTB blocks are resident
__device__ __forceinline__ void grid_sync() {
    __syncthreads();
    if (threadIdx.x == 0) {
        volatile int* vgen = &g_bar_gen;
        int gen = *vgen;
        __threadfence();
        if (atomicAdd(&g_bar_cnt, 1) == TOTB-1) {
            g_bar_cnt = 0;
            __threadfence();
            *vgen = gen + 1;
        } else {
            while (*vgen == gen) { }
        }
        __threadfence();
    }
    __syncthreads();
}

// float 6x6 solve + se3 exp + pose update, run by one thread (cold path)
__device__ void solve_batch(int b, float* __restrict__ out, int write_out) {
    volatile double* a = g_acc + b*27;
    float M[6][7];
    {
        int k=6;
        for (int i=0;i<6;i++)
            for (int j=i;j<6;j++){ float v=(float)a[k]; M[i][j]=v; M[j][i]=v; k++; }
        for (int i=0;i<6;i++){ M[i][i] += 1e-6f; M[i][6] = (float)a[i]; }
    }
    for (int col=0; col<6; col++){
        int piv=col; float best=fabsf(M[col][col]);
        for (int r2=col+1;r2<6;r2++){ float vv=fabsf(M[r2][col]); if (vv>best){best=vv;piv=r2;} }
        if (piv!=col)
            for (int j=0;j<7;j++){ float tmp=M[col][j]; M[col][j]=M[piv][j]; M[piv][j]=tmp; }
        float ip = 1.0f/M[col][col];
        for (int r2=col+1;r2<6;r2++){
            float f = M[r2][col]*ip;
            for (int j=col;j<7;j++) M[r2][j] -= f*M[col][j];
        }
    }
    float xi[6];
    for (int i=5;i>=0;i--){
        float s = M[i][6];
        for (int j=i+1;j<6;j++) s -= M[i][j]*xi[j];
        xi[i] = s/M[i][i];
    }

    float w0=xi[0],w1=xi[1],w2=xi[2],v0=xi[3],v1=xi[4],v2=xi[5];
    float th2 = w0*w0+w1*w1+w2*w2;
    float A,Bc,Cc;
    if (th2 < 1e-8f){
        A = 1.0f - th2/6.0f; Bc = 0.5f - th2/24.0f; Cc = 1.0f/6.0f - th2/120.0f;
    } else {
        float th = sqrtf(th2);
        float s, cth;
        sincosf(th, &s, &cth);
        A = s/th; Bc = (1.0f-cth)/th2; Cc = (th-s)/(th2*th);
    }
    float K[3][3] = {{0.f,-w2,w1},{w2,0.f,-w0},{-w1,w0,0.f}};
    float K2[3][3];
    for (int i=0;i<3;i++)
        for (int j=0;j<3;j++)
            K2[i][j] = K[i][0]*K[0][j]+K[i][1]*K[1][j]+K[i][2]*K[2][j];
    float T[4][4];
    float Vm[3][3];
    for (int i=0;i<3;i++)
        for (int j=0;j<3;j++){
            float I = (i==j)?1.0f:0.0f;
            T[i][j]  = I + A*K[i][j] + Bc*K2[i][j];
            Vm[i][j] = I + Bc*K[i][j] + Cc*K2[i][j];
        }
    T[0][3] = Vm[0][0]*v0+Vm[0][1]*v1+Vm[0][2]*v2;
    T[1][3] = Vm[1][0]*v0+Vm[1][1]*v1+Vm[1][2]*v2;
    T[2][3] = Vm[2][0]*v0+Vm[2][1]*v1+Vm[2][2]*v2;
    T[3][0]=0.0f; T[3][1]=0.0f; T[3][2]=0.0f; T[3][3]=1.0f;

    volatile float* Pg = g_pose + b*16;
    float Pold[4][4];
    for (int i=0;i<4;i++)
        for (int j=0;j<4;j++) Pold[i][j] = Pg[i*4+j];
    float Pn[4][4];
    for (int i=0;i<4;i++)
        for (int j=0;j<4;j++){
            float s=0.0f;
            for (int k=0;k<4;k++) s += T[i][k]*Pold[k][j];
            Pn[i][j]=s;
        }
    for (int i=0;i<4;i++)
        for (int j=0;j<4;j++) Pg[i*4+j] = Pn[i][j];

    for (int k=0;k<27;k++) a[k]=0.0;

    if (write_out){
        for (int i=0;i<4;i++)
            for (int j=0;j<4;j++)
                out[b*16 + i*4 + j] = Pn[i][j];
    }
}

// extract {I0,gx,gy} for channel c (0..3) from the two packed uint4s
__device__ __forceinline__ void get3(const uint4& qa, const uint4& qb, int c,
                                     float& I, float& gx, float& gy) {
    const __half2* h = (c < 2) ? (const __half2*)&qa : (const __half2*)&qb;
    int s = (c & 1) * 2;
    float2 p = __half22float2(h[s]);
    float2 q = __half22float2(h[s+1]);
    I = p.x; gx = p.y; gy = q.x;
}

__global__ void __launch_bounds__(256,4) fused_kernel(
    const float* __restrict__ I0, const float* __restrict__ I1,
    const float* __restrict__ depth0, const float* __restrict__ depth1,
    const float* __restrict__ intr, const float* __restrict__ pose_in,
    float* __restrict__ out)
{
    int tid  = threadIdx.x;
    int lpix = tid & (PIXPB-1);
    int cg   = tid >> 7;                 // channel group: 0 -> ch 0..3 + ICP, 1 -> ch 4..7
    int b    = blockIdx.y;
    int bid  = blockIdx.y*NBLKX + blockIdx.x;   // flat block id 0..TOTB-1

    // ================= phase A: init + precompute =================
    if (bid == 0) {
        if (tid < BB*16) g_pose[tid] = pose_in[tid];
        if (tid < BB*27) g_acc[tid]  = 0.0;
        if (tid < BB)    g_cnt[tid]  = 0;
    }

    for (int idx = bid*256 + tid; idx < BB*HWSZ; idx += TOTB*256) {
        int pb  = idx / HWSZ;
        int pix = idx - pb*HWSZ;
        int x = pix & (WW-1);
        int y = pix / WW;
        float fx = intr[pb*4+0], fy = intr[pb*4+1], cx = intr[pb*4+2], cy = intr[pb*4+3];
        const float* d0 = depth0 + pb*HWSZ;
        int xm = (x>0)? x-1 : 0, xp = (x<WW-1)? x+1 : WW-1;
        int ym = (y>0)? y-1 : 0, yp = (y<HH-1)? y+1 : HH-1;

        float dxm = d0[y*WW+xm], dxp = d0[y*WW+xp];
        float dym = d0[ym*WW+x], dyp = d0[yp*WW+x];
        float dc  = d0[pix];

        float vxm0=((float)xm-cx)/fx*dxm, vxm1=((float)y -cy)/fy*dxm, vxm2=dxm;
        float vxp0=((float)xp-cx)/fx*dxp, vxp1=((float)y -cy)/fy*dxp, vxp2=dxp;
        float vym0=((float)x -cx)/fx*dym, vym1=((float)ym-cy)/fy*dym, vym2=dym;
        float vyp0=((float)x -cx)/fx*dyp, vyp1=((float)yp-cy)/fy*dyp, vyp2=dyp;

        float ax=(vxp0-vxm0)*0.5f, ay=(vxp1-vxm1)*0.5f, az=(vxp2-vxm2)*0.5f;
        float bx=(vyp0-vym0)*0.5f, by=(vyp1-vym1)*0.5f, bz=(vyp2-vym2)*0.5f;

        float nx = ay*bz - az*by;
        float ny = az*bx - ax*bz;
        float nz = ax*by - ay*bx;
        float inv = 1.0f/sqrtf(nx*nx+ny*ny+nz*nz + 1e-12f);
        g_icp[pb*HWSZ + pix] = make_float4(nx*inv, ny*inv, nz*inv, dc);

        __half hbuf[2][16];
        #pragma unroll
        for (int c=0;c<CC;c++){
            const float* Ic = I0 + (size_t)(pb*CC+c)*HWSZ;
            float gx = (Ic[y*WW+xp]-Ic[y*WW+xm])*0.5f;
            float gy = (Ic[yp*WW+x]-Ic[ym*WW+x])*0.5f;
            int g = c >> 2, id4 = (c & 3)*4;
            hbuf[g][id4+0] = __float2half_rn(Ic[pix]);
            hbuf[g][id4+1] = __float2half_rn(gx);
            hbuf[g][id4+2] = __float2half_rn(gy);
            hbuf[g][id4+3] = __float2half_rn(0.0f);
        }
        #pragma unroll
        for (int g=0;g<2;g++){
            const uint4* src = (const uint4*)hbuf[g];
            size_t base = ((size_t)(pb*2+g)*HWSZ + pix)*2;
            g_packh[base+0] = src[0];
            g_packh[base+1] = src[1];
        }
    }

    grid_sync();

    // ================= phase B: 3 GN iterations =================
    float fx = intr[b*4+0], fy = intr[b*4+1], cx = intr[b*4+2], cy = intr[b*4+3];

    for (int it=0; it<3; it++){
        // pose via L2 (written by solver block on another SM within this launch)
        const float* P = g_pose + b*16;
        float R00=__ldcg(P+0), R01=__ldcg(P+1), R02=__ldcg(P+2),  t0=__ldcg(P+3);
        float R10=__ldcg(P+4), R11=__ldcg(P+5), R12=__ldcg(P+6),  t1=__ldcg(P+7);
        float R20=__ldcg(P+8), R21=__ldcg(P+9), R22=__ldcg(P+10), t2=__ldcg(P+11);

        float acc[27];
        #pragma unroll
        for (int k=0;k<27;k++) acc[k]=0.0f;

        #pragma unroll 1
        for (int p=0;p<PPT;p++){
            int pix = blockIdx.x*(PIXPB*PPT) + p*PIXPB + lpix;
            int x = pix & (WW-1), y = pix / WW;

            float d1 = depth1[b*HWSZ+pix];
            float d0c = g_icp[b*HWSZ+pix].w;

            float Vx = ((float)x-cx)/fx*d1;
            float Vy = ((float)y-cy)/fy*d1;
            float Vz = d1;

            float Xx = R00*Vx+R01*Vy+R02*Vz+t0;
            float Xy = R10*Vx+R11*Vy+R12*Vz+t1;
            float Xz = R20*Vx+R21*Vy+R22*Vz+t2;

            bool  valid0 = Xz > 1e-8f;
            float zs = (fabsf(Xz) > 1e-8f) ? Xz : 1e-8f;
            float iz = __fdividef(1.0f, zs);
            float u = fx*Xx*iz + cx;
            float v = fy*Xy*iz + cy;

            bool valid = (u>0.0f) && (u<(float)(WW-1)) && (v>0.0f) && (v<(float)(HH-1))
                       && valid0 && (d0c>0.0f) && (d1>0.0f);
            float vmask = valid ? 1.0f : 0.0f;

            int iu = min(max((int)floorf(u), 0), WW-2);
            int iv = min(max((int)floorf(v), 0), HH-2);
            float du = fminf(fmaxf(u - (float)iu, 0.0f), 1.0f);
            float dv = fminf(fmaxf(v - (float)iv, 0.0f), 1.0f);
            float w00=(1.0f-du)*(1.0f-dv)*vmask, w10=du*(1.0f-dv)*vmask;
            float w01=(1.0f-du)*dv*vmask,        w11=du*dv*vmask;
            int i00 = iv*WW+iu;

            float a  = Xx*iz, bq = Xy*iz;
            float fxz = fx*iz, fyz = fy*iz;
            float Av[6] = { -fx*a*bq,         fx*(1.0f+a*a), -fx*bq, fxz, 0.0f, -fxz*a };
            float Bv[6] = { -fy*(1.0f+bq*bq), fy*a*bq,        fy*a,  0.0f, fyz, -fyz*bq };

            const float*  i1b = I1 + (size_t)(b*CC + cg*4)*HWSZ;
            float i1v[4];
            #pragma unroll
            for (int c=0;c<4;c++) i1v[c] = i1b[(size_t)c*HWSZ + pix];

            const uint4* pk = g_packh + (size_t)(b*2+cg)*HWSZ*2;
            uint4 q00a = pk[(size_t)2*i00],        q00b = pk[(size_t)2*i00+1];
            uint4 q10a = pk[(size_t)2*(i00+1)],    q10b = pk[(size_t)2*(i00+1)+1];
            uint4 q01a = pk[(size_t)2*(i00+WW)],   q01b = pk[(size_t)2*(i00+WW)+1];
            uint4 q11a = pk[(size_t)2*(i00+WW+1)], q11b = pk[(size_t)2*(i00+WW+1)+1];

            float Sxx=0.f, Sxy=0.f, Syy=0.f, Srx=0.f, Sry=0.f;
            #pragma unroll
            for (int c=0;c<4;c++){
                float I00,gx00,gy00, I10,gx10,gy10, I01,gx01,gy01, I11,gx11,gy11;
                get3(q00a,q00b,c, I00,gx00,gy00);
                get3(q10a,q10b,c, I10,gx10,gy10);
                get3(q01a,q01b,c, I01,gx01,gy01);
                get3(q11a,q11b,c, I11,gx11,gy11);
                float s  = w00*I00  + w10*I10  + w01*I01  + w11*I11;
                float gx = w00*gx00 + w10*gx10 + w01*gx01 + w11*gx11;
                float gy = w00*gy00 + w10*gy10 + w01*gy01 + w11*gy11;
                float r = i1v[c] - s;
                float ar = fabsf(r);
                float w  = (ar <= 0.5f) ? 1.0f : __fdividef(0.5f, fmaxf(ar, 1e-12f));
                Sxx += w*gx*gx;
                Sxy += w*gx*gy;
                Syy += w*gy*gy;
                Srx += w*r*gx;
                Sry += w*r*gy;
            }

            {
                #pragma unroll
                for (int i=0;i<6;i++) acc[i] += Srx*Av[i] + Sry*Bv[i];
                int k=6;
                #pragma unroll
                for (int i=0;i<6;i++){
                    float xA = Sxx*Av[i] + Sxy*Bv[i];
                    float xB = Sxy*Av[i] + Syy*Bv[i];
                    #pragma unroll
                    for (int j=i;j<6;j++){
                        acc[k] += xA*Av[j] + xB*Bv[j];
                        k++;
                    }
                }
            }

            if (cg == 0) {
                const float4* ip = g_icp + b*HWSZ;
                float4 e00 = ip[i00];
                float4 e10 = ip[i00+1];
                float4 e01 = ip[i00+WW];
                float4 e11 = ip[i00+WW+1];

                float pxl = ((float)iu    -cx)/fx, pxr = ((float)(iu+1)-cx)/fx;
                float pyt = ((float)iv    -cy)/fy, pyb = ((float)(iv+1)-cy)/fy;
                float rVx = w00*pxl*e00.w + w10*pxr*e10.w + w01*pxl*e01.w + w11*pxr*e11.w;
                float rVy = w00*pyt*e00.w + w10*pyt*e10.w + w01*pyb*e01.w + w11*pyb*e11.w;
                float rVz = w00*e00.w + w10*e10.w + w01*e01.w + w11*e11.w;

                float rNx = w00*e00.x + w10*e10.x + w01*e01.x + w11*e11.x;
                float rNy = w00*e00.y + w10*e10.y + w01*e01.y + w11*e11.y;
                float rNz = w00*e00.z + w10*e10.z + w01*e01.z + w11*e11.z;

                float dfx = Xx - rVx, dfy = Xy - rVy, dfz = Xz - rVz;
                float dn2 = dfx*dfx+dfy*dfy+dfz*dfz + 1e-12f;
                bool occ = dn2 > 0.01f;

                float nR0 = rNx*R00 + rNy*R10 + rNz*R20;
                float nR1 = rNx*R01 + rNy*R11 + rNz*R21;
                float nR2 = rNx*R02 + rNy*R12 + rNz*R22;

                float res = rNx*dfx + rNy*dfy + rNz*dfz;

                float sd0 = d1 * (5.5f/525.0f);
                float sd2 = d1*d1 * (0.4f/(525.0f*1.2f));
                float cov = (nR0*nR0 + nR1*nR1)*sd0*sd0 + nR2*nR2*sd2*sd2;
                float sigma = sqrtf(cov + 1e-8f);
                float isig = __fdividef(1.0f, sigma + 1e-8f);

                res *= isig;
                if (occ) res = 1e-6f;

                float Jr0 = nR1*Vz - nR2*Vy;
                float Jr1 = nR2*Vx - nR0*Vz;
                float Jr2 = nR0*Vy - nR1*Vx;
                float gis = GEOMW*isig;
                float J[6] = { -Jr0*gis, -Jr1*gis, -Jr2*gis, nR0*gis, nR1*gis, nR2*gis };
                float r = -GEOMW * res;
                float ar = fabsf(r);
                float w  = (ar <= 0.5f) ? 1.0f : __fdividef(0.5f, fmaxf(ar, 1e-12f));
                float wr = w*r;
                #pragma unroll
                for (int i=0;i<6;i++) acc[i] += J[i]*wr;
                int k=6;
                #pragma unroll
                for (int i=0;i<6;i++){
                    float wJi = w*J[i];
                    #pragma unroll
                    for (int j=i;j<6;j++){
                        acc[k] += wJi*J[j];
                        k++;
                    }
                }
            }
        }

        // ---- reduction ----
        __shared__ float  sredf[27];
        __shared__ bool amLast;
        if (tid < 27) sredf[tid] = 0.0f;
        __syncthreads();
        #pragma unroll
        for (int k=0;k<27;k++){
            float val = acc[k];
            val += __shfl_down_sync(0xffffffffu, val, 8);
            val += __shfl_down_sync(0xffffffffu, val, 4);
            val += __shfl_down_sync(0xffffffffu, val, 2);
            val += __shfl_down_sync(0xffffffffu, val, 1);
            if ((tid & 15) == 0) atomicAdd(&sredf[k], val);
        }
        __syncthreads();
        if (tid < 27) atomicAdd(&g_acc[b*27+tid], (double)sredf[tid]);

        // ---- last block of this batch solves ----
        __threadfence();
        __syncthreads();
        if (tid == 0){
            int prev = atomicAdd(&g_cnt[b], 1);
            amLast = (prev == NBLKX-1);
        }
        __syncthreads();
        if (amLast && tid == 0){
            __threadfence();
            solve_batch(b, out, (it==2) ? 1 : 0);
            g_cnt[b] = 0;
        }

        grid_sync();   // everyone sees updated pose (via __ldcg) next iteration
    }
}

extern "C" void kernel_launch(void* const* d_in, const int* in_sizes, int n_in,
                              void* d_out, int out_size) {
    const float* pose   = (const float*)d_in[0];
    const float* I0     = (const float*)d_in[1];
    const float* I1     = (const float*)d_in[2];
    const float* intr   = (const float*)d_in[5];
    const float* depth0 = (const float*)d_in[6];
    const float* depth1 = (const float*)d_in[7];
    (void)in_sizes; (void)n_in; (void)out_size;

    dim3 grid(NBLKX, BB);
    fused_kernel<<<grid,256>>>(I0, I1, depth0, depth1, intr, pose, (float*)d_out);
}

// round 16
// speedup vs baseline: 1.6192x; 1.6192x over previous
#include <cuda_runtime.h>
#include <cuda_fp16.h>
#include <math.h>

#define BB 4
#define CC 8
#define HH 192
#define WW 256
#define HWSZ (HH*WW)
#define GEOMW 0.01f
#define PIXPB 128                 // pixel lanes per block (x2 channel groups = 256 threads)
#define PPT 3                     // pixels per thread
#define NBLKX (HWSZ/(PIXPB*PPT))  // 128 blocks per batch -> grid 512 (single wave @4/SM)

// Static device scratch (no allocations allowed)
// photometric pack: [b][cg][pix] -> 32 bytes = 4 channels x {I0,gx,gy,pad} fp16
__device__ uint4  g_packh[BB*2*HWSZ*2];
__device__ float4 g_icp  [BB*HWSZ];     // {nx, ny, nz, depth0}, layout [b][pix]
__device__ float  g_pose[BB*16];
__device__ double g_acc [BB*27];
__device__ int    g_cnt [BB];

__global__ void __launch_bounds__(256) precompute_kernel(
    const float* __restrict__ I0, const float* __restrict__ depth0,
    const float* __restrict__ intr, const float* __restrict__ pose_in)
{
    int pix = blockIdx.x*256 + threadIdx.x;
    int b = blockIdx.y;

    if (blockIdx.x == 0 && b == 0) {
        int i = threadIdx.x;
        if (i < BB*16) g_pose[i] = pose_in[i];
        if (i < BB*27) g_acc[i]  = 0.0;
        if (i < BB)    g_cnt[i]  = 0;
    }

    int x = pix & (WW-1);
    int y = pix / WW;
    float fx = intr[b*4+0], fy = intr[b*4+1], cx = intr[b*4+2], cy = intr[b*4+3];
    const float* d0 = depth0 + b*HWSZ;
    int xm = (x>0)? x-1 : 0, xp = (x<WW-1)? x+1 : WW-1;
    int ym = (y>0)? y-1 : 0, yp = (y<HH-1)? y+1 : HH-1;

    float dxm = d0[y*WW+xm], dxp = d0[y*WW+xp];
    float dym = d0[ym*WW+x], dyp = d0[yp*WW+x];
    float dc  = d0[pix];

    float vxm0=((float)xm-cx)/fx*dxm, vxm1=((float)y -cy)/fy*dxm, vxm2=dxm;
    float vxp0=((float)xp-cx)/fx*dxp, vxp1=((float)y -cy)/fy*dxp, vxp2=dxp;
    float vym0=((float)x -cx)/fx*dym, vym1=((float)ym-cy)/fy*dym, vym2=dym;
    float vyp0=((float)x -cx)/fx*dyp, vyp1=((float)yp-cy)/fy*dyp, vyp2=dyp;

    float ax=(vxp0-vxm0)*0.5f, ay=(vxp1-vxm1)*0.5f, az=(vxp2-vxm2)*0.5f;
    float bx=(vyp0-vym0)*0.5f, by=(vyp1-vym1)*0.5f, bz=(vyp2-vym2)*0.5f;

    float nx = ay*bz - az*by;
    float ny = az*bx - ax*bz;
    float nz = ax*by - ay*bx;
    float inv = 1.0f/sqrtf(nx*nx+ny*ny+nz*nz + 1e-12f);
    g_icp[b*HWSZ + pix] = make_float4(nx*inv, ny*inv, nz*inv, dc);

    __half hbuf[2][16];
    #pragma unroll
    for (int c=0;c<CC;c++){
        const float* Ic = I0 + (size_t)(b*CC+c)*HWSZ;
        float gx = (Ic[y*WW+xp]-Ic[y*WW+xm])*0.5f;
        float gy = (Ic[yp*WW+x]-Ic[ym*WW+x])*0.5f;
        int cg = c >> 2, idx = (c & 3)*4;
        hbuf[cg][idx+0] = __float2half_rn(Ic[pix]);
        hbuf[cg][idx+1] = __float2half_rn(gx);
        hbuf[cg][idx+2] = __float2half_rn(gy);
        hbuf[cg][idx+3] = __float2half_rn(0.0f);
    }
    #pragma unroll
    for (int cg=0;cg<2;cg++){
        const uint4* src = (const uint4*)hbuf[cg];
        size_t base = ((size_t)(b*2+cg)*HWSZ + pix)*2;
        g_packh[base+0] = src[0];
        g_packh[base+1] = src[1];
    }
}

// float 6x6 solve + se3 exp + pose update, run by one thread
__device__ void solve_batch(int b, float* __restrict__ out, int write_out) {
    double* a = g_acc + b*27;
    float M[6][7];
    {
        int k=6;
        for (int i=0;i<6;i++)
            for (int j=i;j<6;j++){ float v=(float)a[k]; M[i][j]=v; M[j][i]=v; k++; }
        for (int i=0;i<6;i++){ M[i][i] += 1e-6f; M[i][6] = (float)a[i]; }
    }
    for (int col=0; col<6; col++){
        int piv=col; float best=fabsf(M[col][col]);
        for (int r2=col+1;r2<6;r2++){ float vv=fabsf(M[r2][col]); if (vv>best){best=vv;piv=r2;} }
        if (piv!=col)
            for (int j=0;j<7;j++){ float tmp=M[col][j]; M[col][j]=M[piv][j]; M[piv][j]=tmp; }
        float ip = 1.0f/M[col][col];
        for (int r2=col+1;r2<6;r2++){
            float f = M[r2][col]*ip;
            for (int j=col;j<7;j++) M[r2][j] -= f*M[col][j];
        }
    }
    float xi[6];
    for (int i=5;i>=0;i--){
        float s = M[i][6];
        for (int j=i+1;j<6;j++) s -= M[i][j]*xi[j];
        xi[i] = s/M[i][i];
    }

    float w0=xi[0],w1=xi[1],w2=xi[2],v0=xi[3],v1=xi[4],v2=xi[5];
    float th2 = w0*w0+w1*w1+w2*w2;
    float A,Bc,Cc;
    if (th2 < 1e-8f){
        A = 1.0f - th2/6.0f; Bc = 0.5f - th2/24.0f; Cc = 1.0f/6.0f - th2/120.0f;
    } else {
        float th = sqrtf(th2);
        float s, cth;
        sincosf(th, &s, &cth);
        A = s/th; Bc = (1.0f-cth)/th2; Cc = (th-s)/(th2*th);
    }
    float K[3][3] = {{0.f,-w2,w1},{w2,0.f,-w0},{-w1,w0,0.f}};
    float K2[3][3];
    for (int i=0;i<3;i++)
        for (int j=0;j<3;j++)
            K2[i][j] = K[i][0]*K[0][j]+K[i][1]*K[1][j]+K[i][2]*K[2][j];
    float T[4][4];
    float Vm[3][3];
    for (int i=0;i<3;i++)
        for (int j=0;j<3;j++){
            float I = (i==j)?1.0f:0.0f;
            T[i][j]  = I + A*K[i][j] + Bc*K2[i][j];
            Vm[i][j] = I + Bc*K[i][j] + Cc*K2[i][j];
        }
    T[0][3] = Vm[0][0]*v0+Vm[0][1]*v1+Vm[0][2]*v2;
    T[1][3] = Vm[1][0]*v0+Vm[1][1]*v1+Vm[1][2]*v2;
    T[2][3] = Vm[2][0]*v0+Vm[2][1]*v1+Vm[2][2]*v2;
    T[3][0]=0.0f; T[3][1]=0.0f; T[3][2]=0.0f; T[3][3]=1.0f;

    float* Pg = g_pose + b*16;
    float Pold[4][4];
    for (int i=0;i<4;i++)
        for (int j=0;j<4;j++) Pold[i][j] = Pg[i*4+j];
    float Pn[4][4];
    for (int i=0;i<4;i++)
        for (int j=0;j<4;j++){
            float s=0.0f;
            for (int k=0;k<4;k++) s += T[i][k]*Pold[k][j];
            Pn[i][j]=s;
        }
    for (int i=0;i<4;i++)
        for (int j=0;j<4;j++) Pg[i*4+j] = Pn[i][j];

    for (int k=0;k<27;k++) a[k]=0.0;

    if (write_out){
        for (int i=0;i<4;i++)
            for (int j=0;j<4;j++)
                out[b*16 + i*4 + j] = Pn[i][j];
    }
}

// extract {I0,gx,gy} for channel c (0..3) from the two packed uint4s
__device__ __forceinline__ void get3(const uint4& qa, const uint4& qb, int c,
                                     float& I, float& gx, float& gy) {
    const __half2* h = (c < 2) ? (const __half2*)&qa : (const __half2*)&qb;
    int s = (c & 1) * 2;
    float2 p = __half22float2(h[s]);
    float2 q = __half22float2(h[s+1]);
    I = p.x; gx = p.y; gy = q.x;
}

__global__ void __launch_bounds__(256,4) accumsolve_kernel(
    const float* __restrict__ I1, const float* __restrict__ depth1,
    const float* __restrict__ intr, float* __restrict__ out, int write_out)
{
    int tid  = threadIdx.x;
    int lpix = tid & (PIXPB-1);
    int cg   = tid >> 7;                 // channel group: 0 -> ch 0..3 + ICP, 1 -> ch 4..7
    int b    = blockIdx.y;

    const float* P = g_pose + b*16;
    float R00=P[0],  R01=P[1],  R02=P[2],  t0=P[3];
    float R10=P[4],  R11=P[5],  R12=P[6],  t1=P[7];
    float R20=P[8],  R21=P[9],  R22=P[10], t2=P[11];

    float fx = intr[b*4+0], fy = intr[b*4+1], cx = intr[b*4+2], cy = intr[b*4+3];

    float acc[27];
    #pragma unroll
    for (int k=0;k<27;k++) acc[k]=0.0f;

    #pragma unroll 1
    for (int p=0;p<PPT;p++){
        int pix = blockIdx.x*(PIXPB*PPT) + p*PIXPB + lpix;
        int x = pix & (WW-1), y = pix / WW;

        float d1 = depth1[b*HWSZ+pix];
        float d0c = g_icp[b*HWSZ+pix].w;

        float Vx = ((float)x-cx)/fx*d1;
        float Vy = ((float)y-cy)/fy*d1;
        float Vz = d1;

        float Xx = R00*Vx+R01*Vy+R02*Vz+t0;
        float Xy = R10*Vx+R11*Vy+R12*Vz+t1;
        float Xz = R20*Vx+R21*Vy+R22*Vz+t2;

        bool  valid0 = Xz > 1e-8f;
        float zs = (fabsf(Xz) > 1e-8f) ? Xz : 1e-8f;
        float iz = __fdividef(1.0f, zs);
        float u = fx*Xx*iz + cx;
        float v = fy*Xy*iz + cy;

        bool valid = (u>0.0f) && (u<(float)(WW-1)) && (v>0.0f) && (v<(float)(HH-1))
                   && valid0 && (d0c>0.0f) && (d1>0.0f);
        float vmask = valid ? 1.0f : 0.0f;

        // branchless clamped bilinear setup
        int iu = min(max((int)floorf(u), 0), WW-2);
        int iv = min(max((int)floorf(v), 0), HH-2);
        float du = fminf(fmaxf(u - (float)iu, 0.0f), 1.0f);
        float dv = fminf(fmaxf(v - (float)iv, 0.0f), 1.0f);
        float w00=(1.0f-du)*(1.0f-dv)*vmask, w10=du*(1.0f-dv)*vmask;
        float w01=(1.0f-du)*dv*vmask,        w11=du*dv*vmask;
        int i00 = iv*WW+iu;

        float a  = Xx*iz, bq = Xy*iz;
        float fxz = fx*iz, fyz = fy*iz;
        // A = row0 of Jw (A[4]=0), B = row1 of Jw (B[3]=0)
        float Av[6] = { -fx*a*bq,         fx*(1.0f+a*a), -fx*bq, fxz, 0.0f, -fxz*a };
        float Bv[6] = { -fy*(1.0f+bq*bq), fy*a*bq,        fy*a,  0.0f, fyz, -fyz*bq };

        // front-load the 4 coalesced I1 reads for this channel group
        const float*  i1b = I1 + (size_t)(b*CC + cg*4)*HWSZ;
        float i1v[4];
        #pragma unroll
        for (int c=0;c<4;c++) i1v[c] = i1b[(size_t)c*HWSZ + pix];

        // ---- photometric: 8 x LDG.128 fetch all 4 channels at 4 corners ----
        const uint4* pk = g_packh + (size_t)(b*2+cg)*HWSZ*2;
        uint4 q00a = pk[(size_t)2*i00],        q00b = pk[(size_t)2*i00+1];
        uint4 q10a = pk[(size_t)2*(i00+1)],    q10b = pk[(size_t)2*(i00+1)+1];
        uint4 q01a = pk[(size_t)2*(i00+WW)],   q01b = pk[(size_t)2*(i00+WW)+1];
        uint4 q11a = pk[(size_t)2*(i00+WW+1)], q11b = pk[(size_t)2*(i00+WW+1)+1];

        float Sxx=0.f, Sxy=0.f, Syy=0.f, Srx=0.f, Sry=0.f;
        #pragma unroll
        for (int c=0;c<4;c++){
            float I00,gx00,gy00, I10,gx10,gy10, I01,gx01,gy01, I11,gx11,gy11;
            get3(q00a,q00b,c, I00,gx00,gy00);
            get3(q10a,q10b,c, I10,gx10,gy10);
            get3(q01a,q01b,c, I01,gx01,gy01);
            get3(q11a,q11b,c, I11,gx11,gy11);
            float s  = w00*I00  + w10*I10  + w01*I01  + w11*I11;
            float gx = w00*gx00 + w10*gx10 + w01*gx01 + w11*gx11;
            float gy = w00*gy00 + w10*gy10 + w01*gy01 + w11*gy11;
            float r = i1v[c] - s;
            float ar = fabsf(r);
            float w  = (ar <= 0.5f) ? 1.0f : __fdividef(0.5f, fmaxf(ar, 1e-12f));
            Sxx += w*gx*gx;
            Sxy += w*gx*gy;
            Syy += w*gy*gy;
            Srx += w*r*gx;
            Sry += w*r*gy;
        }

        {
            #pragma unroll
            for (int i=0;i<6;i++) acc[i] += Srx*Av[i] + Sry*Bv[i];
            int k=6;
            #pragma unroll
            for (int i=0;i<6;i++){
                float xA = Sxx*Av[i] + Sxy*Bv[i];
                float xB = Sxy*Av[i] + Syy*Bv[i];
                #pragma unroll
                for (int j=i;j<6;j++){
                    acc[k] += xA*Av[j] + xB*Bv[j];
                    k++;
                }
            }
        }

        // ---- ICP channel (group 0 only; warp-uniform branch) ----
        if (cg == 0) {
            const float4* ip = g_icp + b*HWSZ;
            float4 e00 = ip[i00];
            float4 e10 = ip[i00+1];
            float4 e01 = ip[i00+WW];
            float4 e11 = ip[i00+WW+1];

            float pxl = ((float)iu    -cx)/fx, pxr = ((float)(iu+1)-cx)/fx;
            float pyt = ((float)iv    -cy)/fy, pyb = ((float)(iv+1)-cy)/fy;
            float rVx = w00*pxl*e00.w + w10*pxr*e10.w + w01*pxl*e01.w + w11*pxr*e11.w;
            float rVy = w00*pyt*e00.w + w10*pyt*e10.w + w01*pyb*e01.w + w11*pyb*e11.w;
            float rVz = w00*e00.w + w10*e10.w + w01*e01.w + w11*e11.w;

            float rNx = w00*e00.x + w10*e10.x + w01*e01.x + w11*e11.x;
            float rNy = w00*e00.y + w10*e10.y + w01*e01.y + w11*e11.y;
            float rNz = w00*e00.z + w10*e10.z + w01*e01.z + w11*e11.z;

            float dfx = Xx - rVx, dfy = Xy - rVy, dfz = Xz - rVz;
            float dn2 = dfx*dfx+dfy*dfy+dfz*dfz + 1e-12f;
            bool occ = dn2 > 0.01f;    // dn>0.1  (inviews == inb for contributing pixels)

            float nR0 = rNx*R00 + rNy*R10 + rNz*R20;
            float nR1 = rNx*R01 + rNy*R11 + rNz*R21;
            float nR2 = rNx*R02 + rNy*R12 + rNz*R22;

            float res = rNx*dfx + rNy*dfy + rNz*dfz;

            float sd0 = d1 * (5.5f/525.0f);
            float sd2 = d1*d1 * (0.4f/(525.0f*1.2f));
            float cov = (nR0*nR0 + nR1*nR1)*sd0*sd0 + nR2*nR2*sd2*sd2;
            float sigma = sqrtf(cov + 1e-8f);
            float isig = __fdividef(1.0f, sigma + 1e-8f);

            res *= isig;
            if (occ) res = 1e-6f;

            float Jr0 = nR1*Vz - nR2*Vy;
            float Jr1 = nR2*Vx - nR0*Vz;
            float Jr2 = nR0*Vy - nR1*Vx;
            float gis = GEOMW*isig;
            float J[6] = { -Jr0*gis, -Jr1*gis, -Jr2*gis, nR0*gis, nR1*gis, nR2*gis };
            float r = -GEOMW * res;
            float ar = fabsf(r);
            float w  = (ar <= 0.5f) ? 1.0f : __fdividef(0.5f, fmaxf(ar, 1e-12f));
            float wr = w*r;
            #pragma unroll
            for (int i=0;i<6;i++) acc[i] += J[i]*wr;
            int k=6;
            #pragma unroll
            for (int i=0;i<6;i++){
                float wJi = w*J[i];
                #pragma unroll
                for (int j=i;j<6;j++){
                    acc[k] += wJi*J[j];
                    k++;
                }
            }
        }
    }

    // ---- reduction: 4-level shuffles (16-lane halves) -> shared float atomics
    //      -> one double atomic per value per block ----
    __shared__ float  sredf[27];
    __shared__ bool amLast;
    if (tid < 27) sredf[tid] = 0.0f;
    __syncthreads();
    #pragma unroll
    for (int k=0;k<27;k++){
        float val = acc[k];
        val += __shfl_down_sync(0xffffffffu, val, 8);
        val += __shfl_down_sync(0xffffffffu, val, 4);
        val += __shfl_down_sync(0xffffffffu, val, 2);
        val += __shfl_down_sync(0xffffffffu, val, 1);
        if ((tid & 15) == 0) atomicAdd(&sredf[k], val);  // lanes 0 and 16
    }
    __syncthreads();
    if (tid < 27) atomicAdd(&g_acc[b*27+tid], (double)sredf[tid]);

    // ---- last block for this batch performs the solve ----
    __threadfence();
    __syncthreads();
    if (tid == 0){
        int prev = atomicAdd(&g_cnt[b], 1);
        amLast = (prev == NBLKX-1);
    }
    __syncthreads();
    if (amLast && tid == 0){
        __threadfence();
        solve_batch(b, out, write_out);
        g_cnt[b] = 0;
    }
}

extern "C" void kernel_launch(void* const* d_in, const int* in_sizes, int n_in,
                              void* d_out, int out_size) {
    const float* pose   = (const float*)d_in[0];
    const float* I0     = (const float*)d_in[1];
    const float* I1     = (const float*)d_in[2];
    const float* intr   = (const float*)d_in[5];
    const float* depth0 = (const float*)d_in[6];
    const float* depth1 = (const float*)d_in[7];
    (void)in_sizes; (void)n_in; (void)out_size;

    dim3 pgrid(HWSZ/256, BB);
    precompute_kernel<<<pgrid,256>>>(I0, depth0, intr, pose);
    dim3 agrid(NBLKX, BB);
    for (int it=0; it<3; it++){
        accumsolve_kernel<<<agrid,256>>>(I1, depth1, intr, (float*)d_out, (it==2) ? 1 : 0);
    }
}